// round 17
// baseline (speedup 1.0000x reference)
#include <cuda_runtime.h>
#include <cuda_fp16.h>

#define CC 256
#define HH 256
#define VV 10000
#define NB 8
#define TT 256
#define TM1 255

__device__ float g_h1[3*CC*HH];
__device__ float g_h2[3*CC*HH];
__device__ float g_slogit[CC];
__device__ float g_init[CC];
__device__ float g_tl[CC*CC];
__device__ float g_trans[CC*CC];     // log probs
__device__ float g_fwdM[CC*CC];      // [b][a] = exp(trans[a][b])  (fwd scan rows)
__device__ float g_bwdM[CC*CC];      // [a][b] = exp(trans[a][b])  (bwd scan rows)
__device__ float g_term[CC*VV];
__device__ float g_term_lse[CC];
__device__ float g_obs[NB*TT*CC];
__device__ float g_alphas[TM1*NB*CC];
__device__ float g_betas[TM1*NB*CC];
__device__ float g_logZ[NB];
__device__ float g_evidence;
__device__ float g_partials[1024];

__device__ __forceinline__ float blockMax256(float v, volatile float* red) {
    #pragma unroll
    for (int o = 16; o > 0; o >>= 1) v = fmaxf(v, __shfl_xor_sync(0xffffffffu, v, o));
    if ((threadIdx.x & 31) == 0) red[threadIdx.x >> 5] = v;
    __syncthreads();
    float r = red[0];
    #pragma unroll
    for (int i = 1; i < 8; ++i) r = fmaxf(r, red[i]);
    __syncthreads();
    return r;
}

__device__ __forceinline__ float blockSum256(float v, volatile float* red) {
    #pragma unroll
    for (int o = 16; o > 0; o >>= 1) v += __shfl_xor_sync(0xffffffffu, v, o);
    if ((threadIdx.x & 31) == 0) red[threadIdx.x >> 5] = v;
    __syncthreads();
    float r = red[0];
    #pragma unroll
    for (int i = 1; i < 8; ++i) r += red[i];
    __syncthreads();
    return r;
}

// Fast block max over 512 threads via redux.sync (ONE barrier). Needs >=2 other
// barriers between successive calls sharing 'redu' (true in the scan loop).
__device__ __forceinline__ float blockMaxFast512(float v, volatile unsigned* redu) {
    int s = __float_as_int(v);
    unsigned k = (unsigned)s ^ (unsigned)((s >> 31) | 0x80000000);
    asm volatile("redux.sync.max.u32 %0, %0, 0xffffffff;" : "+r"(k));
    if ((threadIdx.x & 31) == 0) redu[threadIdx.x >> 5] = k;
    __syncthreads();
    unsigned km = redu[0];
    #pragma unroll
    for (int i = 1; i < 16; ++i) { unsigned x = redu[i]; km = (x > km) ? x : km; }
    int sm = (km & 0x80000000u) ? (int)(km ^ 0x80000000u) : (int)~km;
    return __int_as_float(sm);
}

// ---------------- 64x64 tile GEMM body (for the small square GEMMs) ----------------
template<bool RELU, bool RES>
__device__ __forceinline__ void gemm_body(const float* __restrict__ A,
                                          const float* __restrict__ W,
                                          const float* __restrict__ bias,
                                          const float* __restrict__ X,
                                          float* __restrict__ Cout, int N) {
    __shared__ float As[16][68];
    __shared__ float Ws[16][68];
    const int m0 = blockIdx.y * 64;
    const int n0 = blockIdx.x * 64;
    const int tid = threadIdx.x;
    const int tx = tid & 15, ty = tid >> 4;
    float acc[4][4] = {};
    for (int k0 = 0; k0 < 256; k0 += 16) {
        #pragma unroll
        for (int i = tid; i < 1024; i += 256) {
            int mm = i >> 4, kk = i & 15;
            As[kk][mm] = A[(m0 + mm) * 256 + k0 + kk];
        }
        #pragma unroll
        for (int i = tid; i < 1024; i += 256) {
            int kk = i >> 6, nn = i & 63;
            int n = n0 + nn;
            Ws[kk][nn] = (n < N) ? W[(size_t)(k0 + kk) * N + n] : 0.f;
        }
        __syncthreads();
        #pragma unroll
        for (int kk = 0; kk < 16; ++kk) {
            float4 av = *(const float4*)&As[kk][ty * 4];
            float4 bv = *(const float4*)&Ws[kk][tx * 4];
            float a[4] = {av.x, av.y, av.z, av.w};
            float b[4] = {bv.x, bv.y, bv.z, bv.w};
            #pragma unroll
            for (int i = 0; i < 4; ++i)
                #pragma unroll
                for (int j = 0; j < 4; ++j)
                    acc[i][j] = fmaf(a[i], b[j], acc[i][j]);
        }
        __syncthreads();
    }
    #pragma unroll
    for (int i = 0; i < 4; ++i) {
        int m = m0 + ty * 4 + i;
        #pragma unroll
        for (int j = 0; j < 4; ++j) {
            int n = n0 + tx * 4 + j;
            if (n < N) {
                float c = acc[i][j] + bias[n];
                if (RELU) c = fmaxf(c, 0.f);
                if (RES)  c += X[m * 256 + n];
                Cout[(size_t)m * N + n] = c;
            }
        }
    }
}

// ---------------- 128x64 tile GEMM body (8x4 per thread) for the wide heads ----------------
template<bool RELU>
__device__ __forceinline__ void gemm_body128(const float* __restrict__ A,
                                             const float* __restrict__ W,
                                             const float* __restrict__ bias,
                                             float* __restrict__ Cout, int N) {
    __shared__ float As[16][136];
    __shared__ float Ws[16][68];
    const int m0 = blockIdx.y * 128;
    const int n0 = blockIdx.x * 64;
    const int tid = threadIdx.x;
    const int tx = tid & 15, ty = tid >> 4;   // ty: 16 row-groups of 8
    float acc[8][4] = {};
    for (int k0 = 0; k0 < 256; k0 += 16) {
        #pragma unroll
        for (int i = tid; i < 2048; i += 256) {
            int mm = i >> 4, kk = i & 15;
            As[kk][mm] = A[(m0 + mm) * 256 + k0 + kk];
        }
        #pragma unroll
        for (int i = tid; i < 1024; i += 256) {
            int kk = i >> 6, nn = i & 63;
            int n = n0 + nn;
            Ws[kk][nn] = (n < N) ? W[(size_t)(k0 + kk) * N + n] : 0.f;
        }
        __syncthreads();
        #pragma unroll
        for (int kk = 0; kk < 16; ++kk) {
            float4 a0 = *(const float4*)&As[kk][ty * 8];
            float4 a1 = *(const float4*)&As[kk][ty * 8 + 4];
            float4 bv = *(const float4*)&Ws[kk][tx * 4];
            float a[8] = {a0.x, a0.y, a0.z, a0.w, a1.x, a1.y, a1.z, a1.w};
            float b[4] = {bv.x, bv.y, bv.z, bv.w};
            #pragma unroll
            for (int i = 0; i < 8; ++i)
                #pragma unroll
                for (int j = 0; j < 4; ++j)
                    acc[i][j] = fmaf(a[i], b[j], acc[i][j]);
        }
        __syncthreads();
    }
    #pragma unroll
    for (int i = 0; i < 8; ++i) {
        int m = m0 + ty * 8 + i;
        #pragma unroll
        for (int j = 0; j < 4; ++j) {
            int n = n0 + tx * 4 + j;
            if (n < N) {
                float c = acc[i][j] + bias[n];
                if (RELU) c = fmaxf(c, 0.f);
                Cout[(size_t)m * N + n] = c;
            }
        }
    }
}

__global__ void __launch_bounds__(256) gemmL1_kernel(
    const float* A0, const float* A1, const float* A2,
    const float* W0, const float* W1, const float* W2,
    const float* b0, const float* b1, const float* b2) {
    int z = blockIdx.z;
    const float* A = (z == 0) ? A0 : (z == 1) ? A1 : A2;
    const float* W = (z == 0) ? W0 : (z == 1) ? W1 : W2;
    const float* b = (z == 0) ? b0 : (z == 1) ? b1 : b2;
    gemm_body<true, false>(A, W, b, nullptr, g_h1 + z * CC * HH, 256);
}

__global__ void __launch_bounds__(256) gemmL2_kernel(
    const float* X0, const float* X1, const float* X2,
    const float* W0, const float* W1, const float* W2,
    const float* b0, const float* b1, const float* b2) {
    int z = blockIdx.z;
    const float* X = (z == 0) ? X0 : (z == 1) ? X1 : X2;
    const float* W = (z == 0) ? W0 : (z == 1) ? W1 : W2;
    const float* b = (z == 0) ? b0 : (z == 1) ? b1 : b2;
    gemm_body<true, true>(g_h1 + z * CC * HH, W, b, X, g_h2 + z * CC * HH, 256);
}

// heads: z=0 term (157x2 tiles of 128x64), z=1 trans (4x2), z=2 start gemv.
__global__ void __launch_bounds__(256) heads_kernel(
    const float* tw3, const float* tb3,
    const float* ew3, const float* eb3,
    const float* sw3, const float* sb3) {
    int z = blockIdx.z;
    if (z == 0) {
        gemm_body128<false>(g_h2 + 2 * CC * HH, ew3, eb3, g_term, VV);
    } else if (z == 1) {
        if (blockIdx.x >= 4) return;
        gemm_body128<false>(g_h2 + 1 * CC * HH, tw3, tb3, g_tl, 256);
    } else {
        if (blockIdx.x != 0 || blockIdx.y != 0) return;
        int m = threadIdx.x;
        float acc = 0.f;
        #pragma unroll 8
        for (int k = 0; k < HH; ++k) acc = fmaf(g_h2[m * HH + k], sw3[k], acc);
        g_slogit[m] = acc + sb3[0];
    }
}

// prep: x<256 -> trans softmax row x; 256<=x<512 -> term lse row x-256; x==512 -> init softmax
__global__ void prep_kernel() {
    __shared__ float red[8];
    int x = blockIdx.x;
    if (x < 256) {
        int a = x, b = threadIdx.x;
        float v = g_tl[a * CC + b];
        float m = blockMax256(v, red);
        float s = blockSum256(__expf(v - m), red);
        float lr = v - m - __logf(s);
        float ex = __expf(lr);
        g_trans[a * CC + b] = lr;
        g_bwdM[a * CC + b] = ex;
        g_fwdM[b * CC + a] = ex;
        return;
    }
    if (x == 512) {
        float v = g_slogit[threadIdx.x];
        float m = blockMax256(v, red);
        float s = blockSum256(__expf(v - m), red);
        g_init[threadIdx.x] = v - m - __logf(s);
        return;
    }
    int st = x - 256;
    const float* row = g_term + (size_t)st * VV;
    float m = -1e30f;
    for (int j = threadIdx.x; j < VV; j += 256) m = fmaxf(m, row[j]);
    m = blockMax256(m, red);
    float s = 0.f;
    for (int j = threadIdx.x; j < VV; j += 256) s += __expf(row[j] - m);
    s = blockSum256(s, red);
    if (threadIdx.x == 0) g_term_lse[st] = m + __logf(s);
}

// obs gather, coalesced writes: one CTA per (n,t) token; thread = state c.
__global__ void obs_kernel(const int* __restrict__ text) {
    int nt = blockIdx.x;
    int tok = text[nt];
    int c = threadIdx.x;
    g_obs[nt * CC + c] = g_term[(size_t)c * VV + tok] - g_term_lse[c];
}

// ---- HMMA m16n8k16 helper (fp16 in, fp32 accum) ----
__device__ __forceinline__ void mma16816(float d[4], const unsigned a[4], const unsigned b[2]) {
    asm volatile(
        "mma.sync.aligned.m16n8k16.row.col.f32.f16.f16.f32 "
        "{%0,%1,%2,%3}, {%4,%5,%6,%7}, {%8,%9}, {%0,%1,%2,%3};"
        : "+f"(d[0]), "+f"(d[1]), "+f"(d[2]), "+f"(d[3])
        : "r"(a[0]), "r"(a[1]), "r"(a[2]), "r"(a[3]), "r"(b[0]), "r"(b[1]));
}

__device__ __forceinline__ unsigned pack_h2(float x, float y) {
    __half2 h = __floats2half2_rn(x, y);
    return *(unsigned*)&h;
}

// One matvec step at 16 warps: warp w owns rows [16w,16w+16). 16 HMMA in 2
// independent chains of depth 8. Lanes (l&3)==0 publish this warp's 16 rows.
__device__ __forceinline__ void mma_step16(const unsigned Af[16][4],
                                           const __half* e_h, float* newv,
                                           int w, int r, int c, int l) {
    float da[4] = {0.f,0.f,0.f,0.f}, db[4] = {0.f,0.f,0.f,0.f};
    #pragma unroll
    for (int kt = 0; kt < 8; ++kt) {
        unsigned b0[2], b1[2];
        b0[0] = *(const unsigned*)&e_h[16 * kt + c];
        b0[1] = *(const unsigned*)&e_h[16 * kt + c + 8];
        b1[0] = *(const unsigned*)&e_h[16 * (kt + 8) + c];
        b1[1] = *(const unsigned*)&e_h[16 * (kt + 8) + c + 8];
        mma16816(da, Af[kt], b0);
        mma16816(db, Af[kt + 8], b1);
    }
    if ((l & 3) == 0) {
        newv[16 * w + r]     = da[0] + db[0];
        newv[16 * w + 8 + r] = da[2] + db[2];
    }
}

// Tensor-core scan: one CTA of 512 threads per (n, dir). Matrix in A-fragments.
__global__ void __launch_bounds__(512) scan_kernel() {
    __shared__ __half e_h[CC];
    __shared__ float newv[CC];
    __shared__ unsigned redu[16];
    const int bx = blockIdx.x;
    const bool fwd = bx < 8;
    const int n = fwd ? bx : bx - 8;
    const int tid = threadIdx.x;
    const int w = tid >> 5, l = tid & 31;
    const int r = l >> 2, c = (l & 3) * 2;
    const bool act = tid < 256;
    const float* M = fwd ? g_bwdM : g_fwdM;  // [row=output][col=summed]

    // Warp w owns rows [16w, 16w+16): 16 k-tiles.
    unsigned Af[16][4];
    #pragma unroll
    for (int kt = 0; kt < 16; ++kt) {
        int R = 16 * w + r;
        int K = 16 * kt + c;
        float2 v00 = *(const float2*)(M + R * 256 + K);
        float2 v10 = *(const float2*)(M + (R + 8) * 256 + K);
        float2 v01 = *(const float2*)(M + R * 256 + K + 8);
        float2 v11 = *(const float2*)(M + (R + 8) * 256 + K + 8);
        Af[kt][0] = pack_h2(v00.x, v00.y);
        Af[kt][1] = pack_h2(v10.x, v10.y);
        Af[kt][2] = pack_h2(v01.x, v01.y);
        Af[kt][3] = pack_h2(v11.x, v11.y);
    }
    __syncthreads();

    if (fwd) {
        float alpha = 0.f;
        for (int t = 0; t < TM1; ++t) {
            float obs_next = act ? g_obs[(n * TT + t + 1) * CC + tid] : 0.f;
            float v = -1e30f;
            if (act) v = (t == 0) ? (g_init[tid] + g_obs[(n * TT) * CC + tid]) : alpha;
            float m = blockMaxFast512(v, redu);        // barrier 1
            if (act) e_h[tid] = __float2half(__expf(v - m));
            __syncthreads();                           // barrier 2
            mma_step16(Af, e_h, newv, w, r, c, l);
            __syncthreads();                           // barrier 3
            if (act) {
                alpha = m + __logf(newv[tid]) + obs_next;
                g_alphas[(t * NB + n) * CC + tid] = alpha;
            }
        }
    } else {
        float carry = 0.f;
        for (int t = TM1 - 1; t >= 0; --t) {
            if (act) g_betas[(t * NB + n) * CC + tid] = carry;
            if (t == 0) break;
            float wv = -1e30f;
            if (act) wv = g_obs[(n * TT + t + 1) * CC + tid] + carry;
            float m = blockMaxFast512(wv, redu);       // barrier 1
            if (act) e_h[tid] = __float2half(__expf(wv - m));
            __syncthreads();                           // barrier 2
            mma_step16(Af, e_h, newv, w, r, c, l);
            __syncthreads();                           // barrier 3
            if (act) carry = m + __logf(newv[tid]);
        }
    }
}

__global__ void logz_ev_kernel(const int* __restrict__ lengths) {
    __shared__ float red[8];
    float ev = 0.f;
    for (int n = 0; n < NB; ++n) {
        float v = g_alphas[((TM1 - 1) * NB + n) * CC + threadIdx.x];
        float m = blockMax256(v, red);
        float s = blockSum256(__expf(v - m), red);
        if (threadIdx.x == 0) g_logZ[n] = m + __logf(s);
        int ti = lengths[n] - 1;
        if (ti < 0) ti = 0;
        if (ti > TM1 - 1) ti = TM1 - 1;
        float v2 = g_alphas[(ti * NB + n) * CC + threadIdx.x];
        float m2 = blockMax256(v2, red);
        float s2 = blockSum256(__expf(v2 - m2), red);
        ev += m2 + __logf(s2);
    }
    if (threadIdx.x == 0) g_evidence = ev;
}

#define ELBO_SMEM ((64 * 256 + 256 + 256 + 64 + 64 + 8) * 4)
__global__ void __launch_bounds__(256) elbo_kernel() {
    extern __shared__ float smf[];
    float* Ts   = smf;
    float* vb   = Ts + 64 * 256;
    float* t0b  = vb + 256;
    float* obsA = t0b + 256;
    float* wa   = obsA + 64;
    float* red  = wa + 64;
    const int n = blockIdx.z;
    const int a0 = blockIdx.y * 64;
    const int tb = blockIdx.x * 8;
    const int b = threadIdx.x;

    for (int i = threadIdx.x; i < 64 * 256; i += 256)
        Ts[i] = g_trans[(a0 + (i >> 8)) * CC + (i & 255)];
    const float lz = g_logZ[n];
    float local = 0.f;

    for (int tt = 0; tt < 8; ++tt) {
        int t = tb + tt;
        if (t >= TM1) break;
        __syncthreads();
        float tz = (t == 0) ? (g_init[b] + g_obs[(n * TT) * CC + b]) : 0.f;
        float ap = (t == 0) ? 0.f : g_alphas[((t - 1) * NB + n) * CC + b];
        t0b[b] = tz;
        vb[b]  = ap + tz - lz;
        if (b < 64) {
            int a = a0 + b;
            float oa = g_obs[(n * TT + t + 1) * CC + a];
            obsA[b] = oa;
            wa[b] = g_betas[(t * NB + n) * CC + a] + oa;
        }
        __syncthreads();
        float vbb = vb[b], tzb = t0b[b];
        #pragma unroll 8
        for (int al = 0; al < 64; ++al) {
            float tr = Ts[al * 256 + b];
            float L  = tr + wa[al] + vbb;
            float ph = tr + obsA[al] + tzb;
            local += __expf(L) * ph;
        }
    }
    __syncthreads();
    float s = blockSum256(local, red);
    if (threadIdx.x == 0)
        g_partials[(blockIdx.z * 4 + blockIdx.y) * 32 + blockIdx.x] = s;
}

__global__ void finalize_kernel(float* __restrict__ out) {
    __shared__ float red[8];
    float s = 0.f;
    for (int i = threadIdx.x; i < 1024; i += 256) s += g_partials[i];
    s = blockSum256(s, red);
    if (threadIdx.x == 0) { out[0] = s; out[1] = g_evidence; }
}

extern "C" void kernel_launch(void* const* d_in, const int* in_sizes, int n_in,
                              void* d_out, int out_size) {
    const int*   text      = (const int*)d_in[0];
    const int*   lengths   = (const int*)d_in[2];
    const float* start_emb = (const float*)d_in[3];
    const float* state_emb = (const float*)d_in[4];
    const float* pre_emb   = (const float*)d_in[5];
    const float* sw1 = (const float*)d_in[6];
    const float* sb1 = (const float*)d_in[7];
    const float* sw2 = (const float*)d_in[8];
    const float* sb2 = (const float*)d_in[9];
    const float* sw3 = (const float*)d_in[10];
    const float* sb3 = (const float*)d_in[11];
    const float* tw1 = (const float*)d_in[12];
    const float* tb1 = (const float*)d_in[13];
    const float* tw2 = (const float*)d_in[14];
    const float* tb2 = (const float*)d_in[15];
    const float* tw3 = (const float*)d_in[16];
    const float* tb3 = (const float*)d_in[17];
    const float* ew1 = (const float*)d_in[18];
    const float* eb1 = (const float*)d_in[19];
    const float* ew2 = (const float*)d_in[20];
    const float* eb2 = (const float*)d_in[21];
    const float* ew3 = (const float*)d_in[22];
    const float* eb3 = (const float*)d_in[23];
    float* out = (float*)d_out;

    cudaFuncSetAttribute(elbo_kernel, cudaFuncAttributeMaxDynamicSharedMemorySize, ELBO_SMEM);

    // launch 0: layer1 of start/trans/term nets
    gemmL1_kernel<<<dim3(4, 4, 3), 256>>>(start_emb, state_emb, pre_emb,
                                          sw1, tw1, ew1, sb1, tb1, eb1);
    // launch 1: layer2 (relu + residual)
    gemmL2_kernel<<<dim3(4, 4, 3), 256>>>(start_emb, state_emb, pre_emb,
                                          sw2, tw2, ew2, sb2, tb2, eb2);
    // launch 2: heads (term GEMM 128x64 tiles + trans GEMM + start gemv)
    heads_kernel<<<dim3(157, 2, 3), 256>>>(tw3, tb3, ew3, eb3, sw3, sb3);
    // launch 3: softmaxes + term lse
    prep_kernel<<<513, 256>>>();
    // launch 4: obs gather (coalesced writes)
    obs_kernel<<<NB * TT, 256>>>(text);
    // launch 5: tensor-core forward/backward scans (512 threads, 16 warps)
    scan_kernel<<<16, 512>>>();
    // launch 6: logZ + evidence
    logz_ev_kernel<<<1, 256>>>(lengths);
    // launch 7: elbo accumulation
    elbo_kernel<<<dim3(32, 4, 8), 256, ELBO_SMEM>>>();
    // launch 8: final reduction
    finalize_kernel<<<1, 256>>>(out);
}